// round 1
// baseline (speedup 1.0000x reference)
#include <cuda_runtime.h>
#include <math.h>

// ---------------- problem constants ----------------
#define N_CAM   2
#define PH      96
#define PW      144
#define NPTS    200
#define MIN_D   1.0f
#define MAX_D   4000.0f
#define VD      32
#define VH      128
#define VW      384
#define VOXELSZ 2.5f

#define DHW   (VD*VH*VW)
#define HW    (VH*VW)
#define NRAYS (N_CAM*PH*PW)
#define STEP_D ((MAX_D - MIN_D) / (float)(NPTS - 1))

// half extents (match reference)
#define HX (VOXELSZ * (VW - 1) * 0.5f)
#define HY (VOXELSZ * (VH - 1) * 0.5f)
#define HZ (VOXELSZ * (VD - 1) * 0.5f)

__device__ __forceinline__ float huber01(float x, float y) {
    float d = x - y;
    float v = fmaf(d * d, 100.0f, 1.0f);     // 1 + diff^2/0.1^2  (clip@1e-4 is a no-op: v>=1)
    return (sqrtf(v) - 1.0f) * 0.1f;          // already >= 0, abs() is a no-op
}

__global__ void zero_out_kernel(float* out) {
    if (threadIdx.x < 3) out[threadIdx.x] = 0.0f;
}

// One thread per ray.
__global__ void render_loss_kernel(
    const float* __restrict__ dens,   // (VD,VH,VW)
    const float* __restrict__ cols,   // (3,VD,VH,VW)
    const float* __restrict__ tsil,   // (N_CAM,PH,PW)
    const float* __restrict__ timg,   // (N_CAM,PH,PW,3)
    const float* __restrict__ focal,  // (N_CAM,2)
    const float* __restrict__ princ,  // (N_CAM,2)
    const float* __restrict__ Rm,     // (N_CAM,3,3)
    const float* __restrict__ Tv,     // (N_CAM,3)
    float* __restrict__ out)
{
    int idx = blockIdx.x * blockDim.x + threadIdx.x;
    float csum = 0.0f, ssum = 0.0f;
    if (idx < NRAYS) {
        int w = idx % PW;
        int h = (idx / PW) % PH;
        int n = idx / (PW * PH);

        float fx = focal[n*2+0], fy = focal[n*2+1];
        float px = princ[n*2+0], py = princ[n*2+1];
        float dcx = ((float)w + 0.5f - px) / fx;
        float dcy = ((float)h + 0.5f - py) / fy;

        const float* R = Rm + n*9;
        float Tx = Tv[n*3+0], Ty = Tv[n*3+1], Tz = Tv[n*3+2];

        // dirs_world[j] = sum_k dirs_cam[k] * R[j,k];  origin[j] = -sum_k T[k]*R[j,k]
        float dx = dcx*R[0] + dcy*R[1] + R[2];
        float dy = dcx*R[3] + dcy*R[4] + R[5];
        float dz = dcx*R[6] + dcy*R[7] + R[8];
        float ox = -(Tx*R[0] + Ty*R[1] + Tz*R[2]);
        float oy = -(Tx*R[3] + Ty*R[4] + Tz*R[5]);
        float oz = -(Tx*R[6] + Ty*R[7] + Tz*R[8]);

        // grid coords: g_a(t) = ((o_a + t*d_a)/h_a + 1) * 0.5*(N_a-1)
        // linear form for slab test: g = A + B*t
        const float cx = 0.5f * (VW - 1), cy = 0.5f * (VH - 1), cz = 0.5f * (VD - 1);
        float Ax = ox / HX * cx + cx, Bx = dx / HX * cx;
        float Ay = oy / HY * cy + cy, By = dy / HY * cy;
        float Az = oz / HZ * cz + cz, Bz = dz / HZ * cz;

        float tmin = MIN_D, tmax = MAX_D;
        // slab per axis: nonzero contribution only while g in (-1, N); widen conservatively
        {
            const float lo = -1.001f, hi = (float)VW + 0.001f;
            if (fabsf(Bx) > 1e-20f) {
                float t1 = (lo - Ax) / Bx, t2 = (hi - Ax) / Bx;
                tmin = fmaxf(tmin, fminf(t1, t2)); tmax = fminf(tmax, fmaxf(t1, t2));
            } else if (Ax <= lo || Ax >= hi) { tmax = tmin - 1.0f; }
        }
        {
            const float lo = -1.001f, hi = (float)VH + 0.001f;
            if (fabsf(By) > 1e-20f) {
                float t1 = (lo - Ay) / By, t2 = (hi - Ay) / By;
                tmin = fmaxf(tmin, fminf(t1, t2)); tmax = fminf(tmax, fmaxf(t1, t2));
            } else if (Ay <= lo || Ay >= hi) { tmax = tmin - 1.0f; }
        }
        {
            const float lo = -1.001f, hi = (float)VD + 0.001f;
            if (fabsf(Bz) > 1e-20f) {
                float t1 = (lo - Az) / Bz, t2 = (hi - Az) / Bz;
                tmin = fmaxf(tmin, fminf(t1, t2)); tmax = fminf(tmax, fmaxf(t1, t2));
            } else if (Az <= lo || Az >= hi) { tmax = tmin - 1.0f; }
        }

        int i0 = 0, i1 = -1;
        if (tmax >= tmin) {
            i0 = (int)ceilf ((tmin - MIN_D) / STEP_D - 1e-4f);
            i1 = (int)floorf((tmax - MIN_D) / STEP_D + 1e-4f);
            if (i0 < 0) i0 = 0;
            if (i1 > NPTS - 1) i1 = NPTS - 1;
        }

        float trans = 1.0f;                 // prod(1-d); in fp32, (1+1e-10-d) == (1-d)
        float fr = 0.0f, fg = 0.0f, fb = 0.0f;

        for (int i = i0; i <= i1; ++i) {
            float t = fmaf((float)i, STEP_D, MIN_D);
            float ptx = fmaf(t, dx, ox);
            float pty = fmaf(t, dy, oy);
            float ptz = fmaf(t, dz, oz);
            // exactly the reference mapping
            float gx = (ptx / HX + 1.0f) * (0.5f * (VW - 1));
            float gy = (pty / HY + 1.0f) * (0.5f * (VH - 1));
            float gz = (ptz / HZ + 1.0f) * (0.5f * (VD - 1));

            float x0f = floorf(gx), y0f = floorf(gy), z0f = floorf(gz);
            float frx = gx - x0f, fry = gy - y0f, frz = gz - z0f;
            int ix0 = (int)x0f, iy0 = (int)y0f, iz0 = (int)z0f;

            float wx[2] = {1.0f - frx, frx};
            float wy[2] = {1.0f - fry, fry};
            float wz[2] = {1.0f - frz, frz};
            bool vx[2] = {ix0 >= 0 && ix0 < VW, ix0 + 1 >= 0 && ix0 + 1 < VW};
            bool vy[2] = {iy0 >= 0 && iy0 < VH, iy0 + 1 >= 0 && iy0 + 1 < VH};
            bool vz[2] = {iz0 >= 0 && iz0 < VD, iz0 + 1 >= 0 && iz0 + 1 < VD};

            float ad = 0.0f, ar = 0.0f, ag = 0.0f, ab = 0.0f;
            #pragma unroll
            for (int cdz = 0; cdz < 2; ++cdz) {
                if (!vz[cdz]) continue;
                int zb = (iz0 + cdz) * HW;
                float wzv = wz[cdz];
                #pragma unroll
                for (int cdy = 0; cdy < 2; ++cdy) {
                    if (!vy[cdy]) continue;
                    int yb = zb + (iy0 + cdy) * VW;
                    float wzy = wzv * wy[cdy];
                    #pragma unroll
                    for (int cdx = 0; cdx < 2; ++cdx) {
                        if (!vx[cdx]) continue;
                        int f = yb + ix0 + cdx;
                        float wt = wzy * wx[cdx];
                        ad = fmaf(wt, __ldg(dens + f),            ad);
                        ar = fmaf(wt, __ldg(cols + f),            ar);
                        ag = fmaf(wt, __ldg(cols + f + DHW),      ag);
                        ab = fmaf(wt, __ldg(cols + f + 2*DHW),    ab);
                    }
                }
            }

            float wgt = ad * trans;
            fr = fmaf(wgt, ar, fr);
            fg = fmaf(wgt, ag, fg);
            fb = fmaf(wgt, ab, fb);
            trans *= (1.0f - ad);
        }

        float opacity = 1.0f - trans;

        ssum = huber01(opacity, tsil[idx]);
        const float* ti = timg + (size_t)idx * 3;
        csum = huber01(fr, ti[0]) + huber01(fg, ti[1]) + huber01(fb, ti[2]);
    }

    // warp reduce then one atomic per warp
    #pragma unroll
    for (int o = 16; o > 0; o >>= 1) {
        csum += __shfl_down_sync(0xffffffffu, csum, o);
        ssum += __shfl_down_sync(0xffffffffu, ssum, o);
    }
    if ((threadIdx.x & 31) == 0) {
        atomicAdd(out + 0, csum * (1.0f / (float)(NRAYS * 3)));
        atomicAdd(out + 1, ssum * (1.0f / (float)NRAYS));
    }
}

// BEV: mean over (H,W) of |max over D|
__global__ void bev_kernel(const float* __restrict__ dens, float* __restrict__ out) {
    int idx = blockIdx.x * blockDim.x + threadIdx.x;
    float v = 0.0f;
    if (idx < HW) {
        float m = __ldg(dens + idx);
        #pragma unroll
        for (int z = 1; z < VD; ++z)
            m = fmaxf(m, __ldg(dens + idx + z * HW));
        v = fabsf(m);
    }
    #pragma unroll
    for (int o = 16; o > 0; o >>= 1)
        v += __shfl_down_sync(0xffffffffu, v, o);
    if ((threadIdx.x & 31) == 0)
        atomicAdd(out + 2, v * (1.0f / (float)HW));
}

extern "C" void kernel_launch(void* const* d_in, const int* in_sizes, int n_in,
                              void* d_out, int out_size) {
    const float* dens  = (const float*)d_in[0];
    const float* cols  = (const float*)d_in[1];
    const float* tsil  = (const float*)d_in[2];
    const float* timg  = (const float*)d_in[3];
    const float* focal = (const float*)d_in[4];
    const float* princ = (const float*)d_in[5];
    const float* Rm    = (const float*)d_in[6];
    const float* Tv    = (const float*)d_in[7];
    float* out = (float*)d_out;

    zero_out_kernel<<<1, 32>>>(out);

    int threads = 256;
    int blocks = (NRAYS + threads - 1) / threads;   // 108
    render_loss_kernel<<<blocks, threads>>>(dens, cols, tsil, timg, focal, princ, Rm, Tv, out);

    int bblocks = (HW + threads - 1) / threads;     // 192
    bev_kernel<<<bblocks, threads>>>(dens, out);
}

// round 2
// speedup vs baseline: 1.3170x; 1.3170x over previous
#include <cuda_runtime.h>
#include <math.h>

// ---------------- problem constants ----------------
#define N_CAM   2
#define PH      96
#define PW      144
#define NPTS    200
#define MIN_D   1.0f
#define MAX_D   4000.0f
#define VD      32
#define VH      128
#define VW      384
#define VOXELSZ 2.5f

#define DHW   (VD*VH*VW)
#define HW    (VH*VW)
#define NRAYS (N_CAM*PH*PW)
#define STEP_D ((MAX_D - MIN_D) / (float)(NPTS - 1))

#define HX (VOXELSZ * (VW - 1) * 0.5f)
#define HY (VOXELSZ * (VH - 1) * 0.5f)
#define HZ (VOXELSZ * (VD - 1) * 0.5f)

#define THREADS    256
#define RAY_BLOCKS ((NRAYS + THREADS - 1) / THREADS)        // 108
#define BEV_BLOCKS ((HW / 4 + THREADS - 1) / THREADS)       // 48
#define NBLOCKS    (RAY_BLOCKS + BEV_BLOCKS)                // 156

// scratch for deterministic cross-block reduction (overwritten every replay)
__device__ float    g_partial[NBLOCKS][3];
__device__ unsigned g_count = 0;

__device__ __forceinline__ float huber01(float x, float y) {
    float d = x - y;
    float v = fmaf(d * d, 100.0f, 1.0f);     // 1 + diff^2/0.1^2 (clip@1e-4 no-op)
    return (sqrtf(v) - 1.0f) * 0.1f;         // >= 0, abs() no-op
}

__global__ void __launch_bounds__(THREADS)
fused_loss_kernel(
    const float* __restrict__ dens,   // (VD,VH,VW)
    const float* __restrict__ cols,   // (3,VD,VH,VW)
    const float* __restrict__ tsil,   // (N_CAM,PH,PW)
    const float* __restrict__ timg,   // (N_CAM,PH,PW,3)
    const float* __restrict__ focal,
    const float* __restrict__ princ,
    const float* __restrict__ Rm,
    const float* __restrict__ Tv,
    float* __restrict__ out)
{
    __shared__ float s_a[THREADS/32], s_b[THREADS/32];
    __shared__ bool  s_last;

    const int tid  = threadIdx.x;
    const int lane = tid & 31;
    const int warp = tid >> 5;

    float p0 = 0.0f, p1 = 0.0f, p2 = 0.0f;   // this block's partial (c, s, b)

    if (blockIdx.x < RAY_BLOCKS) {
        // ---------------- ray blocks ----------------
        int idx = blockIdx.x * THREADS + tid;
        float csum = 0.0f, ssum = 0.0f;
        if (idx < NRAYS) {
            int w = idx % PW;
            int h = (idx / PW) % PH;
            int n = idx / (PW * PH);

            float fx = focal[n*2+0], fy = focal[n*2+1];
            float px = princ[n*2+0], py = princ[n*2+1];
            float dcx = ((float)w + 0.5f - px) / fx;
            float dcy = ((float)h + 0.5f - py) / fy;

            const float* R = Rm + n*9;
            float Tx = Tv[n*3+0], Ty = Tv[n*3+1], Tz = Tv[n*3+2];

            float dx = dcx*R[0] + dcy*R[1] + R[2];
            float dy = dcx*R[3] + dcy*R[4] + R[5];
            float dz = dcx*R[6] + dcy*R[7] + R[8];
            float ox = -(Tx*R[0] + Ty*R[1] + Tz*R[2]);
            float oy = -(Tx*R[3] + Ty*R[4] + Tz*R[5]);
            float oz = -(Tx*R[6] + Ty*R[7] + Tz*R[8]);

            // slab test in grid space: g = A + B*t, nonzero only for g in (-1, N)
            const float cx = 0.5f * (VW - 1), cy = 0.5f * (VH - 1), cz = 0.5f * (VD - 1);
            float Ax = ox / HX * cx + cx, Bx = dx / HX * cx;
            float Ay = oy / HY * cy + cy, By = dy / HY * cy;
            float Az = oz / HZ * cz + cz, Bz = dz / HZ * cz;

            float tmin = MIN_D, tmax = MAX_D;
            {
                const float lo = -1.001f, hi = (float)VW + 0.001f;
                if (fabsf(Bx) > 1e-20f) {
                    float t1 = (lo - Ax) / Bx, t2 = (hi - Ax) / Bx;
                    tmin = fmaxf(tmin, fminf(t1, t2)); tmax = fminf(tmax, fmaxf(t1, t2));
                } else if (Ax <= lo || Ax >= hi) { tmax = tmin - 1.0f; }
            }
            {
                const float lo = -1.001f, hi = (float)VH + 0.001f;
                if (fabsf(By) > 1e-20f) {
                    float t1 = (lo - Ay) / By, t2 = (hi - Ay) / By;
                    tmin = fmaxf(tmin, fminf(t1, t2)); tmax = fminf(tmax, fmaxf(t1, t2));
                } else if (Ay <= lo || Ay >= hi) { tmax = tmin - 1.0f; }
            }
            {
                const float lo = -1.001f, hi = (float)VD + 0.001f;
                if (fabsf(Bz) > 1e-20f) {
                    float t1 = (lo - Az) / Bz, t2 = (hi - Az) / Bz;
                    tmin = fmaxf(tmin, fminf(t1, t2)); tmax = fminf(tmax, fmaxf(t1, t2));
                } else if (Az <= lo || Az >= hi) { tmax = tmin - 1.0f; }
            }

            int i0 = 0, i1 = -1;
            if (tmax >= tmin) {
                i0 = (int)ceilf ((tmin - MIN_D) / STEP_D - 1e-4f);
                i1 = (int)floorf((tmax - MIN_D) / STEP_D + 1e-4f);
                if (i0 < 0) i0 = 0;
                if (i1 > NPTS - 1) i1 = NPTS - 1;
            }

            float trans = 1.0f;       // (1+1e-10-d) == (1-d) in fp32
            float fr = 0.0f, fg = 0.0f, fb = 0.0f;

            for (int i = i0; i <= i1; ++i) {
                float t = fmaf((float)i, STEP_D, MIN_D);
                float ptx = fmaf(t, dx, ox);
                float pty = fmaf(t, dy, oy);
                float ptz = fmaf(t, dz, oz);
                float gx = (ptx / HX + 1.0f) * (0.5f * (VW - 1));
                float gy = (pty / HY + 1.0f) * (0.5f * (VH - 1));
                float gz = (ptz / HZ + 1.0f) * (0.5f * (VD - 1));

                float x0f = floorf(gx), y0f = floorf(gy), z0f = floorf(gz);
                float frx = gx - x0f, fry = gy - y0f, frz = gz - z0f;
                int ix0 = (int)x0f, iy0 = (int)y0f, iz0 = (int)z0f;

                float wx[2] = {1.0f - frx, frx};
                float wy[2] = {1.0f - fry, fry};
                float wz[2] = {1.0f - frz, frz};
                bool vx[2] = {ix0 >= 0 && ix0 < VW, ix0 + 1 >= 0 && ix0 + 1 < VW};
                bool vy[2] = {iy0 >= 0 && iy0 < VH, iy0 + 1 >= 0 && iy0 + 1 < VH};
                bool vz[2] = {iz0 >= 0 && iz0 < VD, iz0 + 1 >= 0 && iz0 + 1 < VD};

                float ad = 0.0f, ar = 0.0f, ag = 0.0f, ab = 0.0f;
                #pragma unroll
                for (int cdz = 0; cdz < 2; ++cdz) {
                    if (!vz[cdz]) continue;
                    int zb = (iz0 + cdz) * HW;
                    float wzv = wz[cdz];
                    #pragma unroll
                    for (int cdy = 0; cdy < 2; ++cdy) {
                        if (!vy[cdy]) continue;
                        int yb = zb + (iy0 + cdy) * VW;
                        float wzy = wzv * wy[cdy];
                        #pragma unroll
                        for (int cdx = 0; cdx < 2; ++cdx) {
                            if (!vx[cdx]) continue;
                            int f = yb + ix0 + cdx;
                            float wt = wzy * wx[cdx];
                            ad = fmaf(wt, __ldg(dens + f),         ad);
                            ar = fmaf(wt, __ldg(cols + f),         ar);
                            ag = fmaf(wt, __ldg(cols + f + DHW),   ag);
                            ab = fmaf(wt, __ldg(cols + f + 2*DHW), ab);
                        }
                    }
                }

                float wgt = ad * trans;
                fr = fmaf(wgt, ar, fr);
                fg = fmaf(wgt, ag, fg);
                fb = fmaf(wgt, ab, fb);
                trans *= (1.0f - ad);
            }

            float opacity = 1.0f - trans;
            ssum = huber01(opacity, tsil[idx]);
            const float* ti = timg + (size_t)idx * 3;
            csum = huber01(fr, ti[0]) + huber01(fg, ti[1]) + huber01(fb, ti[2]);
        }

        // block reduce csum, ssum
        #pragma unroll
        for (int o = 16; o > 0; o >>= 1) {
            csum += __shfl_down_sync(0xffffffffu, csum, o);
            ssum += __shfl_down_sync(0xffffffffu, ssum, o);
        }
        if (lane == 0) { s_a[warp] = csum; s_b[warp] = ssum; }
        __syncthreads();
        if (warp == 0) {
            float a = (lane < THREADS/32) ? s_a[lane] : 0.0f;
            float b = (lane < THREADS/32) ? s_b[lane] : 0.0f;
            #pragma unroll
            for (int o = 4; o > 0; o >>= 1) {
                a += __shfl_down_sync(0xffffffffu, a, o);
                b += __shfl_down_sync(0xffffffffu, b, o);
            }
            if (lane == 0) { p0 = a; p1 = b; }
        }
    } else {
        // ---------------- BEV blocks: mean |max_z dens| ----------------
        int cidx = (blockIdx.x - RAY_BLOCKS) * THREADS + tid;   // float4 column index
        float bsum = 0.0f;
        if (cidx < HW / 4) {
            const float4* d4 = (const float4*)dens;
            float4 m = __ldg(d4 + cidx);
            #pragma unroll
            for (int z = 1; z < VD; ++z) {
                float4 v = __ldg(d4 + cidx + z * (HW / 4));
                m.x = fmaxf(m.x, v.x); m.y = fmaxf(m.y, v.y);
                m.z = fmaxf(m.z, v.z); m.w = fmaxf(m.w, v.w);
            }
            bsum = fabsf(m.x) + fabsf(m.y) + fabsf(m.z) + fabsf(m.w);
        }
        #pragma unroll
        for (int o = 16; o > 0; o >>= 1)
            bsum += __shfl_down_sync(0xffffffffu, bsum, o);
        if (lane == 0) s_a[warp] = bsum;
        __syncthreads();
        if (warp == 0) {
            float a = (lane < THREADS/32) ? s_a[lane] : 0.0f;
            #pragma unroll
            for (int o = 4; o > 0; o >>= 1)
                a += __shfl_down_sync(0xffffffffu, a, o);
            if (lane == 0) p2 = a;
        }
    }

    // ---------------- publish partial, last block reduces ----------------
    if (tid == 0) {
        g_partial[blockIdx.x][0] = p0;
        g_partial[blockIdx.x][1] = p1;
        g_partial[blockIdx.x][2] = p2;
        __threadfence();
        unsigned prev = atomicAdd(&g_count, 1u);
        s_last = (prev == NBLOCKS - 1);
    }
    __syncthreads();

    if (s_last) {
        float a = 0.0f, b = 0.0f, c = 0.0f;
        if (tid < NBLOCKS) {
            a = g_partial[tid][0];
            b = g_partial[tid][1];
            c = g_partial[tid][2];
        }
        #pragma unroll
        for (int o = 16; o > 0; o >>= 1) {
            a += __shfl_down_sync(0xffffffffu, a, o);
            b += __shfl_down_sync(0xffffffffu, b, o);
            c += __shfl_down_sync(0xffffffffu, c, o);
        }
        __shared__ float r_a[THREADS/32], r_b[THREADS/32], r_c[THREADS/32];
        if (lane == 0) { r_a[warp] = a; r_b[warp] = b; r_c[warp] = c; }
        __syncthreads();
        if (warp == 0) {
            a = (lane < THREADS/32) ? r_a[lane] : 0.0f;
            b = (lane < THREADS/32) ? r_b[lane] : 0.0f;
            c = (lane < THREADS/32) ? r_c[lane] : 0.0f;
            #pragma unroll
            for (int o = 4; o > 0; o >>= 1) {
                a += __shfl_down_sync(0xffffffffu, a, o);
                b += __shfl_down_sync(0xffffffffu, b, o);
                c += __shfl_down_sync(0xffffffffu, c, o);
            }
            if (lane == 0) {
                out[0] = a * (1.0f / (float)(NRAYS * 3));
                out[1] = b * (1.0f / (float)NRAYS);
                out[2] = c * (1.0f / (float)HW);
                g_count = 0;   // reset for next graph replay
            }
        }
    }
}

extern "C" void kernel_launch(void* const* d_in, const int* in_sizes, int n_in,
                              void* d_out, int out_size) {
    const float* dens  = (const float*)d_in[0];
    const float* cols  = (const float*)d_in[1];
    const float* tsil  = (const float*)d_in[2];
    const float* timg  = (const float*)d_in[3];
    const float* focal = (const float*)d_in[4];
    const float* princ = (const float*)d_in[5];
    const float* Rm    = (const float*)d_in[6];
    const float* Tv    = (const float*)d_in[7];
    float* out = (float*)d_out;

    fused_loss_kernel<<<NBLOCKS, THREADS>>>(dens, cols, tsil, timg,
                                            focal, princ, Rm, Tv, out);
}

// round 3
// speedup vs baseline: 1.4486x; 1.1000x over previous
#include <cuda_runtime.h>
#include <math.h>

// ---------------- problem constants ----------------
#define N_CAM   2
#define PH      96
#define PW      144
#define NPTS    200
#define MIN_D   1.0f
#define MAX_D   4000.0f
#define VD      32
#define VH      128
#define VW      384
#define VOXELSZ 2.5f

#define DHW   (VD*VH*VW)
#define HW    (VH*VW)
#define NRAYS (N_CAM*PH*PW)
#define STEP_D ((MAX_D - MIN_D) / (float)(NPTS - 1))

#define HX (VOXELSZ * (VW - 1) * 0.5f)
#define HY (VOXELSZ * (VH - 1) * 0.5f)
#define HZ (VOXELSZ * (VD - 1) * 0.5f)

#define LPR 4                                    // lanes per ray
#define THREADS    256
#define RAY_BLOCKS ((NRAYS * LPR) / THREADS)     // 432 (exact)
#define BEV_BLOCKS ((HW / 4 + THREADS - 1) / THREADS)  // 48
#define NBLOCKS    (RAY_BLOCKS + BEV_BLOCKS)     // 480

// scratch for deterministic cross-block reduction (overwritten every replay)
__device__ float    g_partial[NBLOCKS][3];
__device__ unsigned g_count = 0;

__device__ __forceinline__ float huber01(float x, float y) {
    float d = x - y;
    float v = fmaf(d * d, 100.0f, 1.0f);
    return (sqrtf(v) - 1.0f) * 0.1f;
}

__global__ void __launch_bounds__(THREADS)
fused_loss_kernel(
    const float* __restrict__ dens,   // (VD,VH,VW)
    const float* __restrict__ cols,   // (3,VD,VH,VW)
    const float* __restrict__ tsil,   // (N_CAM,PH,PW)
    const float* __restrict__ timg,   // (N_CAM,PH,PW,3)
    const float* __restrict__ focal,
    const float* __restrict__ princ,
    const float* __restrict__ Rm,
    const float* __restrict__ Tv,
    float* __restrict__ out)
{
    __shared__ float s_a[THREADS/32], s_b[THREADS/32];
    __shared__ bool  s_last;

    const int tid  = threadIdx.x;
    const int lane = tid & 31;
    const int warp = tid >> 5;

    float p0 = 0.0f, p1 = 0.0f, p2 = 0.0f;   // block partials (color, sil, bev)

    if (blockIdx.x < RAY_BLOCKS) {
        // ---------------- ray blocks: LPR lanes per ray ----------------
        int g   = blockIdx.x * THREADS + tid;   // < NRAYS*LPR exactly
        int idx = g >> 2;                        // ray id
        int sub = g & 3;                         // lane-within-ray

        int w = idx % PW;
        int h = (idx / PW) % PH;
        int n = idx / (PW * PH);

        float fx = focal[n*2+0], fy = focal[n*2+1];
        float px = princ[n*2+0], py = princ[n*2+1];
        float dcx = ((float)w + 0.5f - px) / fx;
        float dcy = ((float)h + 0.5f - py) / fy;

        const float* R = Rm + n*9;
        float Tx = Tv[n*3+0], Ty = Tv[n*3+1], Tz = Tv[n*3+2];

        float dx = dcx*R[0] + dcy*R[1] + R[2];
        float dy = dcx*R[3] + dcy*R[4] + R[5];
        float dz = dcx*R[6] + dcy*R[7] + R[8];
        float ox = -(Tx*R[0] + Ty*R[1] + Tz*R[2]);
        float oy = -(Tx*R[3] + Ty*R[4] + Tz*R[5]);
        float oz = -(Tx*R[6] + Ty*R[7] + Tz*R[8]);

        // slab test in grid space: g = A + B*t, nonzero only for g in (-1, N)
        const float cx = 0.5f * (VW - 1), cy = 0.5f * (VH - 1), cz = 0.5f * (VD - 1);
        float Ax = ox / HX * cx + cx, Bx = dx / HX * cx;
        float Ay = oy / HY * cy + cy, By = dy / HY * cy;
        float Az = oz / HZ * cz + cz, Bz = dz / HZ * cz;

        float tmin = MIN_D, tmax = MAX_D;
        {
            const float lo = -1.001f, hi = (float)VW + 0.001f;
            if (fabsf(Bx) > 1e-20f) {
                float t1 = (lo - Ax) / Bx, t2 = (hi - Ax) / Bx;
                tmin = fmaxf(tmin, fminf(t1, t2)); tmax = fminf(tmax, fmaxf(t1, t2));
            } else if (Ax <= lo || Ax >= hi) { tmax = tmin - 1.0f; }
        }
        {
            const float lo = -1.001f, hi = (float)VH + 0.001f;
            if (fabsf(By) > 1e-20f) {
                float t1 = (lo - Ay) / By, t2 = (hi - Ay) / By;
                tmin = fmaxf(tmin, fminf(t1, t2)); tmax = fminf(tmax, fmaxf(t1, t2));
            } else if (Ay <= lo || Ay >= hi) { tmax = tmin - 1.0f; }
        }
        {
            const float lo = -1.001f, hi = (float)VD + 0.001f;
            if (fabsf(Bz) > 1e-20f) {
                float t1 = (lo - Az) / Bz, t2 = (hi - Az) / Bz;
                tmin = fmaxf(tmin, fminf(t1, t2)); tmax = fminf(tmax, fmaxf(t1, t2));
            } else if (Az <= lo || Az >= hi) { tmax = tmin - 1.0f; }
        }

        int i0 = 0, i1 = -1;
        if (tmax >= tmin) {
            i0 = (int)ceilf ((tmin - MIN_D) / STEP_D - 1e-4f);
            i1 = (int)floorf((tmax - MIN_D) / STEP_D + 1e-4f);
            if (i0 < 0) i0 = 0;
            if (i1 > NPTS - 1) i1 = NPTS - 1;
        }

        // this lane's contiguous chunk of samples
        int nsamp = i1 - i0 + 1;                 // may be <= 0
        int chunk = (nsamp + LPR - 1) >> 2;      // per-lane count (>=0)
        int s0 = i0 + sub * chunk;
        int s1 = s0 + chunk - 1;
        if (s1 > i1) s1 = i1;

        float trans = 1.0f;                      // local prod(1-d)
        float fr = 0.0f, fg = 0.0f, fb = 0.0f;   // local over-composited rgb

        for (int i = s0; i <= s1; ++i) {
            float t = fmaf((float)i, STEP_D, MIN_D);
            float ptx = fmaf(t, dx, ox);
            float pty = fmaf(t, dy, oy);
            float ptz = fmaf(t, dz, oz);
            float gx = (ptx / HX + 1.0f) * (0.5f * (VW - 1));
            float gy = (pty / HY + 1.0f) * (0.5f * (VH - 1));
            float gz = (ptz / HZ + 1.0f) * (0.5f * (VD - 1));

            float x0f = floorf(gx), y0f = floorf(gy), z0f = floorf(gz);
            float frx = gx - x0f, fry = gy - y0f, frz = gz - z0f;
            int ix0 = (int)x0f, iy0 = (int)y0f, iz0 = (int)z0f;

            float wx[2] = {1.0f - frx, frx};
            float wy[2] = {1.0f - fry, fry};
            float wz[2] = {1.0f - frz, frz};
            bool vx[2] = {ix0 >= 0 && ix0 < VW, ix0 + 1 >= 0 && ix0 + 1 < VW};
            bool vy[2] = {iy0 >= 0 && iy0 < VH, iy0 + 1 >= 0 && iy0 + 1 < VH};
            bool vz[2] = {iz0 >= 0 && iz0 < VD, iz0 + 1 >= 0 && iz0 + 1 < VD};

            float ad = 0.0f, ar = 0.0f, ag = 0.0f, ab = 0.0f;
            #pragma unroll
            for (int cdz = 0; cdz < 2; ++cdz) {
                if (!vz[cdz]) continue;
                int zb = (iz0 + cdz) * HW;
                float wzv = wz[cdz];
                #pragma unroll
                for (int cdy = 0; cdy < 2; ++cdy) {
                    if (!vy[cdy]) continue;
                    int yb = zb + (iy0 + cdy) * VW;
                    float wzy = wzv * wy[cdy];
                    #pragma unroll
                    for (int cdx = 0; cdx < 2; ++cdx) {
                        if (!vx[cdx]) continue;
                        int f = yb + ix0 + cdx;
                        float wt = wzy * wx[cdx];
                        ad = fmaf(wt, __ldg(dens + f),         ad);
                        ar = fmaf(wt, __ldg(cols + f),         ar);
                        ag = fmaf(wt, __ldg(cols + f + DHW),   ag);
                        ab = fmaf(wt, __ldg(cols + f + 2*DHW), ab);
                    }
                }
            }

            float wgt = ad * trans;
            fr = fmaf(wgt, ar, fr);
            fg = fmaf(wgt, ag, fg);
            fb = fmaf(wgt, ab, fb);
            trans *= (1.0f - ad);
        }

        // ---- compose the 4 lane-chunks: (F,T) ⊗ (F',T') = (F + T F', T T') ----
        // step 1: combine (0,1) and (2,3); step 2: lane0 combines with lane2.
        {
            float Tn  = __shfl_down_sync(0xffffffffu, trans, 1, LPR);
            float frn = __shfl_down_sync(0xffffffffu, fr,    1, LPR);
            float fgn = __shfl_down_sync(0xffffffffu, fg,    1, LPR);
            float fbn = __shfl_down_sync(0xffffffffu, fb,    1, LPR);
            fr = fmaf(trans, frn, fr);
            fg = fmaf(trans, fgn, fg);
            fb = fmaf(trans, fbn, fb);
            trans *= Tn;

            Tn  = __shfl_down_sync(0xffffffffu, trans, 2, LPR);
            frn = __shfl_down_sync(0xffffffffu, fr,    2, LPR);
            fgn = __shfl_down_sync(0xffffffffu, fg,    2, LPR);
            fbn = __shfl_down_sync(0xffffffffu, fb,    2, LPR);
            fr = fmaf(trans, frn, fr);
            fg = fmaf(trans, fgn, fg);
            fb = fmaf(trans, fbn, fb);
            trans *= Tn;
        }

        float csum = 0.0f, ssum = 0.0f;
        if (sub == 0) {
            float opacity = 1.0f - trans;
            ssum = huber01(opacity, tsil[idx]);
            const float* ti = timg + (size_t)idx * 3;
            csum = huber01(fr, ti[0]) + huber01(fg, ti[1]) + huber01(fb, ti[2]);
        }

        // block reduce
        #pragma unroll
        for (int o = 16; o > 0; o >>= 1) {
            csum += __shfl_down_sync(0xffffffffu, csum, o);
            ssum += __shfl_down_sync(0xffffffffu, ssum, o);
        }
        if (lane == 0) { s_a[warp] = csum; s_b[warp] = ssum; }
        __syncthreads();
        if (warp == 0) {
            float a = (lane < THREADS/32) ? s_a[lane] : 0.0f;
            float b = (lane < THREADS/32) ? s_b[lane] : 0.0f;
            #pragma unroll
            for (int o = 4; o > 0; o >>= 1) {
                a += __shfl_down_sync(0xffffffffu, a, o);
                b += __shfl_down_sync(0xffffffffu, b, o);
            }
            if (lane == 0) { p0 = a; p1 = b; }
        }
    } else {
        // ---------------- BEV blocks: mean |max_z dens| ----------------
        int cidx = (blockIdx.x - RAY_BLOCKS) * THREADS + tid;   // float4 column index
        float bsum = 0.0f;
        if (cidx < HW / 4) {
            const float4* d4 = (const float4*)dens;
            float4 m = __ldg(d4 + cidx);
            #pragma unroll
            for (int z = 1; z < VD; ++z) {
                float4 v = __ldg(d4 + cidx + z * (HW / 4));
                m.x = fmaxf(m.x, v.x); m.y = fmaxf(m.y, v.y);
                m.z = fmaxf(m.z, v.z); m.w = fmaxf(m.w, v.w);
            }
            bsum = fabsf(m.x) + fabsf(m.y) + fabsf(m.z) + fabsf(m.w);
        }
        #pragma unroll
        for (int o = 16; o > 0; o >>= 1)
            bsum += __shfl_down_sync(0xffffffffu, bsum, o);
        if (lane == 0) s_a[warp] = bsum;
        __syncthreads();
        if (warp == 0) {
            float a = (lane < THREADS/32) ? s_a[lane] : 0.0f;
            #pragma unroll
            for (int o = 4; o > 0; o >>= 1)
                a += __shfl_down_sync(0xffffffffu, a, o);
            if (lane == 0) p2 = a;
        }
    }

    // ---------------- publish partial, last block reduces ----------------
    if (tid == 0) {
        g_partial[blockIdx.x][0] = p0;
        g_partial[blockIdx.x][1] = p1;
        g_partial[blockIdx.x][2] = p2;
        __threadfence();
        unsigned prev = atomicAdd(&g_count, 1u);
        s_last = (prev == NBLOCKS - 1);
    }
    __syncthreads();

    if (s_last) {
        float a = 0.0f, b = 0.0f, c = 0.0f;
        for (int i = tid; i < NBLOCKS; i += THREADS) {
            a += g_partial[i][0];
            b += g_partial[i][1];
            c += g_partial[i][2];
        }
        #pragma unroll
        for (int o = 16; o > 0; o >>= 1) {
            a += __shfl_down_sync(0xffffffffu, a, o);
            b += __shfl_down_sync(0xffffffffu, b, o);
            c += __shfl_down_sync(0xffffffffu, c, o);
        }
        __shared__ float r_a[THREADS/32], r_b[THREADS/32], r_c[THREADS/32];
        if (lane == 0) { r_a[warp] = a; r_b[warp] = b; r_c[warp] = c; }
        __syncthreads();
        if (warp == 0) {
            a = (lane < THREADS/32) ? r_a[lane] : 0.0f;
            b = (lane < THREADS/32) ? r_b[lane] : 0.0f;
            c = (lane < THREADS/32) ? r_c[lane] : 0.0f;
            #pragma unroll
            for (int o = 4; o > 0; o >>= 1) {
                a += __shfl_down_sync(0xffffffffu, a, o);
                b += __shfl_down_sync(0xffffffffu, b, o);
                c += __shfl_down_sync(0xffffffffu, c, o);
            }
            if (lane == 0) {
                out[0] = a * (1.0f / (float)(NRAYS * 3));
                out[1] = b * (1.0f / (float)NRAYS);
                out[2] = c * (1.0f / (float)HW);
                g_count = 0;   // reset for next graph replay
            }
        }
    }
}

extern "C" void kernel_launch(void* const* d_in, const int* in_sizes, int n_in,
                              void* d_out, int out_size) {
    const float* dens  = (const float*)d_in[0];
    const float* cols  = (const float*)d_in[1];
    const float* tsil  = (const float*)d_in[2];
    const float* timg  = (const float*)d_in[3];
    const float* focal = (const float*)d_in[4];
    const float* princ = (const float*)d_in[5];
    const float* Rm    = (const float*)d_in[6];
    const float* Tv    = (const float*)d_in[7];
    float* out = (float*)d_out;

    fused_loss_kernel<<<NBLOCKS, THREADS>>>(dens, cols, tsil, timg,
                                            focal, princ, Rm, Tv, out);
}